// round 14
// baseline (speedup 1.0000x reference)
#include <cuda_runtime.h>
#include <cstddef>
#include <cstdint>

// Problem constants
#define NB   256            // batch
#define NU   8              // in_units
#define NI   1152           // in_size
#define NJ   10             // out_units
#define ND   16             // out_size
#define NJD  (NJ*ND)        // 160
#define NK   (NU*NI)        // 9216
#define NM   (NJD*NU)       // 1280
#define NPART 36            // exp partial-sums per j (uv_fuse i-blocks)

// Packed fp32x2 helpers (Blackwell sm_103a)
#define FMA_F32X2(acc, a, b) \
    asm("fma.rn.f32x2 %0, %1, %2, %0;" : "+l"(acc) : "l"(a), "l"(b))
#define UNPACK2(lo, hi, in) \
    asm("mov.b64 {%0, %1}, %2;" : "=r"(lo), "=r"(hi) : "l"(in))

// GEMM smem (floats): wide tile [2][32][ASP], dup splat tile [2][32][BSP]
#define ASP    132              // 128 + pad
#define BSP    162              // 80*2 dup + pad
#define AS_F   (2 * 32 * ASP)   // 8448
#define BS_F   (2 * 32 * BSP)   // 10368
#define GEMM_SMEM ((AS_F + BS_F) * 4)   // 75264 B

// Scratch (device globals; allocation-free per harness rules)
__device__ float g_WT  [(size_t)NJD * NU * NI];  // [jd][u][i]  5.9 MB
__device__ float g_G   [(size_t)NJD * NU * NI];  // [jd][u][i]  5.9 MB
__device__ float g_s   [3 * NB * NJD];           // per-iteration s slices
__device__ float g_b   [NJ * NI];                // logits after it0 update [j][i]
__device__ float g_e   [3 * NJ * NI];            // unnormalized exp(b) per iter [j][i]
__device__ float g_part[3 * NJ * NPART];         // per-(iter,j) partial exp-sums

// ---------------------------------------------------------------------------
// Kernel 0 (once per replay): WT[m][i] = W[i][m]; zero g_s; init e/partials
// for iteration 0 (uniform softmax: e=1, NPART partials of 32 -> sum=1152).
// ---------------------------------------------------------------------------
__global__ void prep_kernel(const float* __restrict__ W) {
    __shared__ float t[32][33];
    const int i0 = blockIdx.x * 32, m0 = blockIdx.y * 32;
    const int tx = threadIdx.x, ty = threadIdx.y;
#pragma unroll
    for (int r = 0; r < 4; r++) {
        int i = i0 + ty + 8 * r;
        t[ty + 8 * r][tx] = W[(size_t)i * NM + m0 + tx];
    }
    __syncthreads();
#pragma unroll
    for (int r = 0; r < 4; r++) {
        int m = m0 + ty + 8 * r;
        g_WT[(size_t)m * NI + i0 + tx] = t[tx][ty + 8 * r];
    }

    const int flat = blockIdx.y * gridDim.x + blockIdx.x;   // 0..1439
    const int tid  = ty * 32 + tx;
    if (flat < 480) {                    // zero 3*40960 g_s floats
        g_s[flat * 256 + tid] = 0.0f;
    } else if (flat < 525) {             // e slot 0 = 1.0 (11520 floats)
        g_e[(flat - 480) * 256 + tid] = 1.0f;
    } else if (flat <= 526) {            // partials slot 0 = 32 (36*32 = 1152)
        int idx = (flat - 525) * 256 + tid;
        if (idx < NJ * NPART) g_part[idx] = 32.0f;
    }
}

// ---------------------------------------------------------------------------
// Kernel 1: s_{it}[b,jd] += sum_k x[b,k] * c[i(k),j] * WT[jd,k]
// c = e[it][j][i] * (1/sum_j), sum from NPART partials (prologue).
// M=256 x N=160 x K=9216, split-K x36 (chunk 256). grid (2,2,36), BLOCK 512.
// CTA 128b x 80jd (r11 tile); thread 4b x 5jd. Same grid/tiles/traffic as
// r11, but 16 warps/SM (4/SMSP) instead of 8 -> latency hiding.
// Per warp-kk: 1 LDS.128 (2-addr broadcast) + 5 LDS.64 dup + 10 FFMA2.
// ---------------------------------------------------------------------------
__global__ __launch_bounds__(512) void s_gemm(const float* __restrict__ x, int it) {
    extern __shared__ float sm[];
    float* As = sm;            // [2][32][ASP]  [k][b]
    float* Bs = sm + AS_F;     // [2][32][BSP]  [k][2*jd_local] duplicated
    __shared__ float inv_sm[5];

    const int t   = threadIdx.x;
    const int tx  = t & 15;              // 16 jd-groups of 5
    const int ty  = t >> 4;              // 32 b-groups of 4
    const int b0  = blockIdx.x * 128;
    const int jd0 = blockIdx.y * 80;
    const int k0  = blockIdx.z * 256;
    const int j_lo = jd0 >> 4;

    if (t < 5) {
        const float* pp = g_part + it * (NJ * NPART) + (j_lo + t) * NPART;
        float s = 0.f;
#pragma unroll
        for (int r = 0; r < NPART; r++) s += pp[r];
        inv_sm[t] = 1.0f / s;
    }
    __syncthreads();

    unsigned long long acc2[2][5];
#pragma unroll
    for (int p = 0; p < 2; p++)
#pragma unroll
        for (int q = 0; q < 5; q++) acc2[p][q] = 0ULL;

    float4 af[2];
    float  bf[5];
    const float* e_it = g_e + it * (NJ * NI);

    auto fetch = [&](int kb) {
        const int kbase = k0 + kb * 32;
#pragma unroll
        for (int r = 0; r < 2; r++) {
            int idx4 = t + 512 * r;                 // 1024 f4 = 128b x 8k4
            int bl = idx4 >> 3, k4 = idx4 & 7;
            af[r] = *(const float4*)&x[(size_t)(b0 + bl) * NK + kbase + k4 * 4];
        }
#pragma unroll
        for (int r = 0; r < 5; r++) {
            int idx = t + 512 * r;                  // 2560 = 32k x 80jd
            int kk = idx & 31, col = idx >> 5;
            int kg = kbase + kk;
            int u  = kg / NI;
            int i  = kg - u * NI;
            int jd = jd0 + col;
            int j  = jd >> 4;
            bf[r] = g_WT[(size_t)jd * NK + kg] * e_it[j * NI + i] * inv_sm[j - j_lo];
        }
    };
    auto sts = [&](int buf) {
        float* Ab = As + buf * 32 * ASP;
        float* Bb = Bs + buf * 32 * BSP;
#pragma unroll
        for (int r = 0; r < 2; r++) {
            int idx4 = t + 512 * r;
            int bl = idx4 >> 3, k4 = idx4 & 7;
            Ab[(k4 * 4 + 0) * ASP + bl] = af[r].x;
            Ab[(k4 * 4 + 1) * ASP + bl] = af[r].y;
            Ab[(k4 * 4 + 2) * ASP + bl] = af[r].z;
            Ab[(k4 * 4 + 3) * ASP + bl] = af[r].w;
        }
#pragma unroll
        for (int r = 0; r < 5; r++) {
            int idx = t + 512 * r;
            int kk = idx & 31, col = idx >> 5;
            *(float2*)&Bb[kk * BSP + col * 2] = make_float2(bf[r], bf[r]);
        }
    };

    fetch(0);
    sts(0);
    __syncthreads();

    for (int kb = 0; kb < 8; kb++) {
        const int buf = kb & 1;
        if (kb < 7) fetch(kb + 1);
        const float* Ab = As + buf * 32 * ASP;
        const float* Bb = Bs + buf * 32 * BSP;
#pragma unroll
        for (int kk = 0; kk < 32; kk++) {
            ulonglong2 a01 = *(const ulonglong2*)(Ab + kk * ASP + ty * 4);
#pragma unroll
            for (int q = 0; q < 5; q++) {
                unsigned long long bb =
                    *(const unsigned long long*)&Bb[kk * BSP + (tx * 5 + q) * 2];
                FMA_F32X2(acc2[0][q], a01.x, bb);
                FMA_F32X2(acc2[1][q], a01.y, bb);
            }
        }
        if (kb < 7) {
            sts(buf ^ 1);
            __syncthreads();
        }
    }

    float* sdst = g_s + it * (NB * NJD);
#pragma unroll
    for (int p = 0; p < 2; p++)
#pragma unroll
        for (int q = 0; q < 5; q++) {
            unsigned lo, hi;
            UNPACK2(lo, hi, acc2[p][q]);
            const int jd = jd0 + tx * 5 + q;
            const int b  = b0 + ty * 4 + 2 * p;
            atomicAdd(&sdst[b * NJD + jd], __uint_as_float(lo));
            atomicAdd(&sdst[(b + 1) * NJD + jd], __uint_as_float(hi));
        }
}

// ---------------------------------------------------------------------------
// Kernel 2: G[m, n] = sum_b v[b,m] * x[b,n], with v computed in-prologue:
//   scale[b,d] = sqrt(msq)/(1+msq), msq = sum_j s[b,j,d]^2 ;  v = s * scale
// M=160 x N=9216 x K=256. grid (72,2), BLOCK 512. CTA 80m x 128n (r11 tile);
// thread 5m x 4n. 16 warps/SM.
// ---------------------------------------------------------------------------
__global__ __launch_bounds__(512) void g_gemm(const float* __restrict__ x, int it) {
    extern __shared__ float sm[];
    float* Xs = sm;            // [2][32][ASP]
    float* Vs = sm + AS_F;     // [2][32][BSP] duplicated
    __shared__ float scale_sm[NB * ND];   // 16 KB

    const int t  = threadIdx.x;
    const int tx = t & 15;               // 16 m-groups of 5
    const int ty = t >> 4;               // 32 n-groups of 4
    const int n0 = blockIdx.x * 128;
    const int m0 = blockIdx.y * 80;
    const float* s_it = g_s + it * (NB * NJD);

    // squash scales for all (b,d)
    for (int bd = t; bd < NB * ND; bd += 512) {
        const int b = bd >> 4, d = bd & 15;
        const float* sp = s_it + b * NJD + d;
        float msq = 0.f;
#pragma unroll
        for (int j = 0; j < NJ; j++) {
            float v = sp[j * ND];
            msq = fmaf(v, v, msq);
        }
        scale_sm[bd] = sqrtf(msq) / (1.0f + msq);
    }
    __syncthreads();

    unsigned long long acc2[2][5];
#pragma unroll
    for (int p = 0; p < 2; p++)
#pragma unroll
        for (int q = 0; q < 5; q++) acc2[p][q] = 0ULL;

    float4 xf[2];
    float  vf[5];

    auto fetch = [&](int kb) {
        const int kbase = kb * 32;
#pragma unroll
        for (int r = 0; r < 2; r++) {
            int idx4 = t + 512 * r;                 // 1024 f4 = 32k x 32n4
            int kk = idx4 >> 5, n4 = idx4 & 31;
            xf[r] = *(const float4*)&x[(size_t)(kbase + kk) * NK + n0 + n4 * 4];
        }
#pragma unroll
        for (int r = 0; r < 5; r++) {
            int idx = t + 512 * r;                  // 2560 = 32k x 80m
            int col = idx % 80, kk = idx / 80;
            int b = kbase + kk, m = m0 + col;
            vf[r] = s_it[b * NJD + m] * scale_sm[(b << 4) | (m & 15)];
        }
    };
    auto sts = [&](int buf) {
        float* Xb = Xs + buf * 32 * ASP;
        float* Vb = Vs + buf * 32 * BSP;
#pragma unroll
        for (int r = 0; r < 2; r++) {
            int idx4 = t + 512 * r;
            int kk = idx4 >> 5, n4 = idx4 & 31;
            *(float4*)&Xb[kk * ASP + n4 * 4] = xf[r];
        }
#pragma unroll
        for (int r = 0; r < 5; r++) {
            int idx = t + 512 * r;
            int col = idx % 80, kk = idx / 80;
            *(float2*)&Vb[kk * BSP + col * 2] = make_float2(vf[r], vf[r]);
        }
    };

    fetch(0);
    sts(0);
    __syncthreads();

    for (int kb = 0; kb < 8; kb++) {
        const int buf = kb & 1;
        if (kb < 7) fetch(kb + 1);
        const float* Xb = Xs + buf * 32 * ASP;
        const float* Vb = Vs + buf * 32 * BSP;
#pragma unroll
        for (int kk = 0; kk < 32; kk++) {
            ulonglong2 x01 = *(const ulonglong2*)(Xb + kk * ASP + ty * 4);
#pragma unroll
            for (int q = 0; q < 5; q++) {
                unsigned long long vv =
                    *(const unsigned long long*)&Vb[kk * BSP + (tx * 5 + q) * 2];
                FMA_F32X2(acc2[0][q], x01.x, vv);
                FMA_F32X2(acc2[1][q], x01.y, vv);
            }
        }
        if (kb < 7) {
            sts(buf ^ 1);
            __syncthreads();
        }
    }

    // Store: thread owns m = m0+tx*5+q, n = n0+ty*4 .. +3
#pragma unroll
    for (int q = 0; q < 5; q++) {
        const int m = m0 + tx * 5 + q;
        unsigned l0, h0, l1, h1;
        UNPACK2(l0, h0, acc2[0][q]);
        UNPACK2(l1, h1, acc2[1][q]);
        float4 o;
        o.x = __uint_as_float(l0);
        o.y = __uint_as_float(h0);
        o.z = __uint_as_float(l1);
        o.w = __uint_as_float(h1);
        *(float4*)&g_G[(size_t)m * NK + n0 + ty * 4] = o;
    }
}

// ---------------------------------------------------------------------------
// Kernel 3: fused agreement + b-update + exp + partial sums.
// grid (36, 10) = 360 CTAs, block 256: 32 i's per CTA, 8 m-groups of 16.
// 2x CTAs vs r11 for better latency hiding of the L2-bound reduction.
// ---------------------------------------------------------------------------
__global__ __launch_bounds__(256) void uv_fuse(int it) {
    const int t   = threadIdx.x;
    const int il  = t & 31;            // i within block
    const int grp = t >> 5;            // 8 m-groups of 16
    const int i = blockIdx.x * 32 + il;
    const int j = blockIdx.y;

    const size_t base = (size_t)(j * 128 + grp * 16) * NI + i;
    float acc = 0.f;
#pragma unroll
    for (int m = 0; m < 16; m++) {
        acc = fmaf(g_WT[base + (size_t)m * NI], g_G[base + (size_t)m * NI], acc);
    }

    __shared__ float red[8][32];
    __shared__ float esum[32];
    red[grp][il] = acc;
    __syncthreads();
    if (grp < 4) red[grp][il] += red[grp + 4][il];
    __syncthreads();
    if (grp < 2) red[grp][il] += red[grp + 2][il];
    __syncthreads();
    if (grp == 0) {
        float uv = red[0][il] + red[1][il];
        float bv = (it == 0 ? 1.0f : g_b[j * NI + i]) + uv * (1.0f / (float)NB);
        if (it == 0) g_b[j * NI + i] = bv;
        float e = expf(bv);
        g_e[(it + 1) * (NJ * NI) + j * NI + i] = e;
        esum[il] = e;
    }
    __syncthreads();
    if (t < 32) {
        float v = esum[t];
#pragma unroll
        for (int o = 16; o > 0; o >>= 1) v += __shfl_down_sync(0xffffffffu, v, o);
        if (t == 0)
            g_part[(it + 1) * (NJ * NPART) + j * NPART + blockIdx.x] = v;
    }
}

// ---------------------------------------------------------------------------
// Kernel 4: final squash -> d_out.  v = s * sqrt(msq)/(1+msq), msq over j.
// ---------------------------------------------------------------------------
__global__ void squash_out(float* __restrict__ out) {
    const int t = blockIdx.x * blockDim.x + threadIdx.x;
    if (t >= NB * ND) return;
    const int b = t >> 4, d = t & 15;

    const float* sp = g_s + 2 * (NB * NJD) + b * NJD + d;
    float vals[NJ];
    float msq = 0.f;
#pragma unroll
    for (int j = 0; j < NJ; j++) {
        vals[j] = sp[j * ND];
        msq = fmaf(vals[j], vals[j], msq);
    }
    const float scale = sqrtf(msq) / (1.0f + msq);
#pragma unroll
    for (int j = 0; j < NJ; j++) out[b * NJD + j * ND + d] = vals[j] * scale;
}

// ---------------------------------------------------------------------------
extern "C" void kernel_launch(void* const* d_in, const int* in_sizes, int n_in,
                              void* d_out, int out_size) {
    const float* x = (const float*)d_in[0];   // (256, 8, 1152)
    const float* W = (const float*)d_in[1];   // (1, 1152, 10, 16, 8)
    float* out = (float*)d_out;               // (256, 10, 16, 1)

    static bool attr_set = false;
    if (!attr_set) {
        cudaFuncSetAttribute(s_gemm, cudaFuncAttributeMaxDynamicSharedMemorySize,
                             GEMM_SMEM);
        cudaFuncSetAttribute(g_gemm, cudaFuncAttributeMaxDynamicSharedMemorySize,
                             GEMM_SMEM);
        attr_set = true;
    }

    prep_kernel<<<dim3(36, 40), dim3(32, 8)>>>(W);

    for (int it = 0; it < 3; it++) {
        s_gemm<<<dim3(2, 2, 36), 512, GEMM_SMEM>>>(x, it);
        if (it < 2) {
            g_gemm<<<dim3(72, 2), 512, GEMM_SMEM>>>(x, it);
            uv_fuse<<<dim3(36, NJ), 256>>>(it);
        }
    }
    squash_out<<<16, 256>>>(out);
}

// round 15
// speedup vs baseline: 1.2256x; 1.2256x over previous
#include <cuda_runtime.h>
#include <cstddef>
#include <cstdint>

// Problem constants
#define NB   256            // batch
#define NU   8              // in_units
#define NI   1152           // in_size
#define NJ   10             // out_units
#define ND   16             // out_size
#define NJD  (NJ*ND)        // 160
#define NK   (NU*NI)        // 9216
#define NM   (NJD*NU)       // 1280
#define NPART 18            // exp partial-sums per j (uv_fuse i-blocks)

// Packed fp32x2 helpers (Blackwell sm_103a)
#define FMA_F32X2(acc, a, b) \
    asm("fma.rn.f32x2 %0, %1, %2, %0;" : "+l"(acc) : "l"(a), "l"(b))
#define UNPACK2(lo, hi, in) \
    asm("mov.b64 {%0, %1}, %2;" : "=r"(lo), "=r"(hi) : "l"(in))

// GEMM smem (floats): wide tile [2][32][ASP], dup splat tile [2][32][BSP]
#define ASP    132              // 128 + pad
#define BSP    162              // 80*2 dup + pad
#define AS_F   (2 * 32 * ASP)   // 8448
#define BS_F   (2 * 32 * BSP)   // 10368
#define GEMM_SMEM ((AS_F + BS_F) * 4)   // 75264 B

// Scratch (device globals; allocation-free per harness rules)
__device__ float g_WT  [(size_t)NJD * NU * NI];  // [jd][u][i]  5.9 MB
__device__ float g_G   [(size_t)NJD * NU * NI];  // [jd][u][i]  5.9 MB
__device__ float g_s   [3 * NB * NJD];           // per-iteration s slices
__device__ float g_b   [NJ * NI];                // logits after it0 update [j][i]
__device__ float g_e   [3 * NJ * NI];            // unnormalized exp(b) per iter [j][i]
__device__ float g_part[3 * NJ * NPART];         // per-(iter,j) partial exp-sums

// ---------------------------------------------------------------------------
// Kernel 0 (once per replay): WT[m][i] = W[i][m]; zero g_s; init e/partials
// for iteration 0 (uniform softmax: e=1, NPART partials of 64 -> sum=1152).
// ---------------------------------------------------------------------------
__global__ void prep_kernel(const float* __restrict__ W) {
    __shared__ float t[32][33];
    const int i0 = blockIdx.x * 32, m0 = blockIdx.y * 32;
    const int tx = threadIdx.x, ty = threadIdx.y;
#pragma unroll
    for (int r = 0; r < 4; r++) {
        int i = i0 + ty + 8 * r;
        t[ty + 8 * r][tx] = W[(size_t)i * NM + m0 + tx];
    }
    __syncthreads();
#pragma unroll
    for (int r = 0; r < 4; r++) {
        int m = m0 + ty + 8 * r;
        g_WT[(size_t)m * NI + i0 + tx] = t[tx][ty + 8 * r];
    }

    const int flat = blockIdx.y * gridDim.x + blockIdx.x;   // 0..1439
    const int tid  = ty * 32 + tx;
    if (flat < 480) {                    // zero 3*40960 g_s floats
        g_s[flat * 256 + tid] = 0.0f;
    } else if (flat < 525) {             // e slot 0 = 1.0 (11520 floats)
        g_e[(flat - 480) * 256 + tid] = 1.0f;
    } else if (flat == 525) {            // partials slot 0 = 64 (sum 1152)
        if (tid < NJ * NPART) g_part[tid] = 64.0f;
    }
}

// ---------------------------------------------------------------------------
// Kernel 1: s_{it}[b,jd] += inv_j * sum_k x[b,k] * e[it][j,i(k)] * WT[jd,k]
// inv_j applied in the EPILOGUE (valid per split-K partial: same constant).
// M=256 x N=160 x K=9216, split-K x36 (chunk 256). grid (2,2,36), block 256.
// CTA 128b x 80jd; thread 8b x 5jd (r11-proven broadcast layout).
// ---------------------------------------------------------------------------
__global__ __launch_bounds__(256) void s_gemm(const float* __restrict__ x, int it) {
    extern __shared__ float sm[];
    float* As = sm;            // [2][32][ASP]  [k][b]
    float* Bs = sm + AS_F;     // [2][32][BSP]  [k][2*jd_local] duplicated
    __shared__ float inv_sm[5];

    const int t   = threadIdx.x;
    const int tx  = t & 15;              // 16 jd-groups of 5
    const int ty  = t >> 4;              // 16 b-groups of 8
    const int b0  = blockIdx.x * 128;
    const int jd0 = blockIdx.y * 80;
    const int k0  = blockIdx.z * 256;
    const int j_lo = jd0 >> 4;
    // i(k) without division: chunk of 256 crosses the NI boundary at most once
    const int i_base = k0 % NI;

    if (t < 5) {
        const float* pp = g_part + it * (NJ * NPART) + (j_lo + t) * NPART;
        float s = 0.f;
#pragma unroll
        for (int r = 0; r < NPART; r++) s += pp[r];
        inv_sm[t] = 1.0f / s;
    }

    unsigned long long acc2[4][5];
#pragma unroll
    for (int p = 0; p < 4; p++)
#pragma unroll
        for (int q = 0; q < 5; q++) acc2[p][q] = 0ULL;

    float4 af[4];
    float  bf[10];
    const float* e_it = g_e + it * (NJ * NI);

    auto fetch = [&](int kb) {
        const int kbase = k0 + kb * 32;
        const int ibase = i_base + kb * 32;
#pragma unroll
        for (int r = 0; r < 4; r++) {
            int idx4 = t + 256 * r;                 // 1024 f4 = 128b x 8k4
            int bl = idx4 >> 3, k4 = idx4 & 7;
            af[r] = *(const float4*)&x[(size_t)(b0 + bl) * NK + kbase + k4 * 4];
        }
#pragma unroll
        for (int r = 0; r < 10; r++) {
            int idx = t + 256 * r;                  // 2560 = 32k x 80jd
            int kk = idx & 31, col = idx >> 5;
            int i  = ibase + kk;
            if (i >= NI) i -= NI;
            int jd = jd0 + col;
            int j  = jd >> 4;
            bf[r] = g_WT[(size_t)jd * NK + kbase + kk] * e_it[j * NI + i];
        }
    };
    auto sts = [&](int buf) {
        float* Ab = As + buf * 32 * ASP;
        float* Bb = Bs + buf * 32 * BSP;
#pragma unroll
        for (int r = 0; r < 4; r++) {
            int idx4 = t + 256 * r;
            int bl = idx4 >> 3, k4 = idx4 & 7;
            Ab[(k4 * 4 + 0) * ASP + bl] = af[r].x;
            Ab[(k4 * 4 + 1) * ASP + bl] = af[r].y;
            Ab[(k4 * 4 + 2) * ASP + bl] = af[r].z;
            Ab[(k4 * 4 + 3) * ASP + bl] = af[r].w;
        }
#pragma unroll
        for (int r = 0; r < 10; r++) {
            int idx = t + 256 * r;
            int kk = idx & 31, col = idx >> 5;
            *(float2*)&Bb[kk * BSP + col * 2] = make_float2(bf[r], bf[r]);
        }
    };

    fetch(0);
    sts(0);
    __syncthreads();

    for (int kb = 0; kb < 8; kb++) {
        const int buf = kb & 1;
        if (kb < 7) fetch(kb + 1);
        const float* Ab = As + buf * 32 * ASP;
        const float* Bb = Bs + buf * 32 * BSP;
#pragma unroll
        for (int kk = 0; kk < 32; kk++) {
            const float* arow = Ab + kk * ASP + ty * 8;
            ulonglong2 a01 = *(const ulonglong2*)arow;
            ulonglong2 a23 = *(const ulonglong2*)(arow + 4);
#pragma unroll
            for (int q = 0; q < 5; q++) {
                unsigned long long bb =
                    *(const unsigned long long*)&Bb[kk * BSP + (tx * 5 + q) * 2];
                FMA_F32X2(acc2[0][q], a01.x, bb);
                FMA_F32X2(acc2[1][q], a01.y, bb);
                FMA_F32X2(acc2[2][q], a23.x, bb);
                FMA_F32X2(acc2[3][q], a23.y, bb);
            }
        }
        if (kb < 7) {
            sts(buf ^ 1);
            __syncthreads();
        }
    }

    float* sdst = g_s + it * (NB * NJD);
#pragma unroll
    for (int p = 0; p < 4; p++)
#pragma unroll
        for (int q = 0; q < 5; q++) {
            unsigned lo, hi;
            UNPACK2(lo, hi, acc2[p][q]);
            const int jd = jd0 + tx * 5 + q;
            const float inv = inv_sm[(jd >> 4) - j_lo];
            const int b  = b0 + ty * 8 + 2 * p;
            atomicAdd(&sdst[b * NJD + jd], __uint_as_float(lo) * inv);
            atomicAdd(&sdst[(b + 1) * NJD + jd], __uint_as_float(hi) * inv);
        }
}

// ---------------------------------------------------------------------------
// Kernel 2: G[m, n] = sum_b v[b,m] * x[b,n], with v computed in-prologue:
//   scale[b,d] = sqrt(msq)/(1+msq), msq = sum_j s[b,j,d]^2 ;  v = s * scale
// M=160 x N=9216 x K=256. grid (72,2), block 256. CTA 80m x 128n; thr 5m x 8n.
// (r11 verbatim)
// ---------------------------------------------------------------------------
__global__ __launch_bounds__(256) void g_gemm(const float* __restrict__ x, int it) {
    extern __shared__ float sm[];
    float* Xs = sm;            // [2][32][ASP]
    float* Vs = sm + AS_F;     // [2][32][BSP] duplicated
    __shared__ float scale_sm[NB * ND];   // 16 KB

    const int t  = threadIdx.x;
    const int tx = t & 15;               // 16 m-groups of 5
    const int ty = t >> 4;               // 16 n-groups of 8
    const int n0 = blockIdx.x * 128;
    const int m0 = blockIdx.y * 80;
    const float* s_it = g_s + it * (NB * NJD);

    // squash scales for all (b,d)
    for (int bd = t; bd < NB * ND; bd += 256) {
        const int b = bd >> 4, d = bd & 15;
        const float* sp = s_it + b * NJD + d;
        float msq = 0.f;
#pragma unroll
        for (int j = 0; j < NJ; j++) {
            float v = sp[j * ND];
            msq = fmaf(v, v, msq);
        }
        scale_sm[bd] = sqrtf(msq) / (1.0f + msq);
    }
    __syncthreads();

    unsigned long long acc2[4][5];
#pragma unroll
    for (int p = 0; p < 4; p++)
#pragma unroll
        for (int q = 0; q < 5; q++) acc2[p][q] = 0ULL;

    float4 xf[4];
    float  vf[10];

    auto fetch = [&](int kb) {
        const int kbase = kb * 32;
#pragma unroll
        for (int r = 0; r < 4; r++) {
            int idx4 = t + 256 * r;                 // 1024 f4 = 32k x 32n4
            int kk = idx4 >> 5, n4 = idx4 & 31;
            xf[r] = *(const float4*)&x[(size_t)(kbase + kk) * NK + n0 + n4 * 4];
        }
#pragma unroll
        for (int r = 0; r < 10; r++) {
            int idx = t + 256 * r;                  // 2560 = 32k x 80m
            int col = idx % 80, kk = idx / 80;
            int b = kbase + kk, m = m0 + col;
            vf[r] = s_it[b * NJD + m] * scale_sm[(b << 4) | (m & 15)];
        }
    };
    auto sts = [&](int buf) {
        float* Xb = Xs + buf * 32 * ASP;
        float* Vb = Vs + buf * 32 * BSP;
#pragma unroll
        for (int r = 0; r < 4; r++) {
            int idx4 = t + 256 * r;
            int kk = idx4 >> 5, n4 = idx4 & 31;
            *(float4*)&Xb[kk * ASP + n4 * 4] = xf[r];
        }
#pragma unroll
        for (int r = 0; r < 10; r++) {
            int idx = t + 256 * r;
            int col = idx % 80, kk = idx / 80;
            *(float2*)&Vb[kk * BSP + col * 2] = make_float2(vf[r], vf[r]);
        }
    };

    fetch(0);
    sts(0);
    __syncthreads();

    for (int kb = 0; kb < 8; kb++) {
        const int buf = kb & 1;
        if (kb < 7) fetch(kb + 1);
        const float* Xb = Xs + buf * 32 * ASP;
        const float* Vb = Vs + buf * 32 * BSP;
#pragma unroll
        for (int kk = 0; kk < 32; kk++) {
            const float* xrow = Xb + kk * ASP + ty * 8;
            ulonglong2 x01 = *(const ulonglong2*)xrow;
            ulonglong2 x23 = *(const ulonglong2*)(xrow + 4);
#pragma unroll
            for (int q = 0; q < 5; q++) {
                unsigned long long vv =
                    *(const unsigned long long*)&Vb[kk * BSP + (tx * 5 + q) * 2];
                FMA_F32X2(acc2[0][q], x01.x, vv);
                FMA_F32X2(acc2[1][q], x01.y, vv);
                FMA_F32X2(acc2[2][q], x23.x, vv);
                FMA_F32X2(acc2[3][q], x23.y, vv);
            }
        }
        if (kb < 7) {
            sts(buf ^ 1);
            __syncthreads();
        }
    }

#pragma unroll
    for (int q = 0; q < 5; q++) {
        const int m = m0 + tx * 5 + q;
        unsigned l0, h0, l1, h1, l2, h2, l3, h3;
        UNPACK2(l0, h0, acc2[0][q]);
        UNPACK2(l1, h1, acc2[1][q]);
        UNPACK2(l2, h2, acc2[2][q]);
        UNPACK2(l3, h3, acc2[3][q]);
        float4 o0, o1;
        o0.x = __uint_as_float(l0); o0.y = __uint_as_float(h0);
        o0.z = __uint_as_float(l1); o0.w = __uint_as_float(h1);
        o1.x = __uint_as_float(l2); o1.y = __uint_as_float(h2);
        o1.z = __uint_as_float(l3); o1.w = __uint_as_float(h3);
        float* dst = &g_G[(size_t)m * NK + n0 + ty * 8];
        *(float4*)dst = o0;
        *(float4*)(dst + 4) = o1;
    }
}

// ---------------------------------------------------------------------------
// Kernel 3: fused agreement + b-update + exp + partial sums. (r11-proven)
// grid (18, 10), block 512: 64 i's per CTA, 8 m-groups of 16 per thread.
// ---------------------------------------------------------------------------
__global__ __launch_bounds__(512) void uv_fuse(int it) {
    const int t   = threadIdx.x;
    const int il  = t & 63;            // i within block
    const int grp = t >> 6;            // 8 m-groups of 16
    const int i = blockIdx.x * 64 + il;
    const int j = blockIdx.y;

    const size_t base = (size_t)(j * 128 + grp * 16) * NI + i;
    float acc = 0.f;
#pragma unroll
    for (int m = 0; m < 16; m++) {
        acc = fmaf(g_WT[base + (size_t)m * NI], g_G[base + (size_t)m * NI], acc);
    }

    __shared__ float red[8][64];
    __shared__ float esum[64];
    red[grp][il] = acc;
    __syncthreads();
    if (grp < 4) red[grp][il] += red[grp + 4][il];
    __syncthreads();
    if (grp < 2) red[grp][il] += red[grp + 2][il];
    __syncthreads();
    if (grp == 0) {
        float uv = red[0][il] + red[1][il];
        float bv = (it == 0 ? 1.0f : g_b[j * NI + i]) + uv * (1.0f / (float)NB);
        if (it == 0) g_b[j * NI + i] = bv;
        float e = expf(bv);
        g_e[(it + 1) * (NJ * NI) + j * NI + i] = e;
        esum[il] = e;
    }
    __syncthreads();
    if (t < 32) {
        float v = esum[t] + esum[t + 32];
#pragma unroll
        for (int o = 16; o > 0; o >>= 1) v += __shfl_down_sync(0xffffffffu, v, o);
        if (t == 0)
            g_part[(it + 1) * (NJ * NPART) + j * NPART + blockIdx.x] = v;
    }
}

// ---------------------------------------------------------------------------
// Kernel 4: final squash -> d_out.  v = s * sqrt(msq)/(1+msq), msq over j.
// ---------------------------------------------------------------------------
__global__ void squash_out(float* __restrict__ out) {
    const int t = blockIdx.x * blockDim.x + threadIdx.x;
    if (t >= NB * ND) return;
    const int b = t >> 4, d = t & 15;

    const float* sp = g_s + 2 * (NB * NJD) + b * NJD + d;
    float vals[NJ];
    float msq = 0.f;
#pragma unroll
    for (int j = 0; j < NJ; j++) {
        vals[j] = sp[j * ND];
        msq = fmaf(vals[j], vals[j], msq);
    }
    const float scale = sqrtf(msq) / (1.0f + msq);
#pragma unroll
    for (int j = 0; j < NJ; j++) out[b * NJD + j * ND + d] = vals[j] * scale;
}

// ---------------------------------------------------------------------------
extern "C" void kernel_launch(void* const* d_in, const int* in_sizes, int n_in,
                              void* d_out, int out_size) {
    const float* x = (const float*)d_in[0];   // (256, 8, 1152)
    const float* W = (const float*)d_in[1];   // (1, 1152, 10, 16, 8)
    float* out = (float*)d_out;               // (256, 10, 16, 1)

    static bool attr_set = false;
    if (!attr_set) {
        cudaFuncSetAttribute(s_gemm, cudaFuncAttributeMaxDynamicSharedMemorySize,
                             GEMM_SMEM);
        cudaFuncSetAttribute(g_gemm, cudaFuncAttributeMaxDynamicSharedMemorySize,
                             GEMM_SMEM);
        attr_set = true;
    }

    prep_kernel<<<dim3(36, 40), dim3(32, 8)>>>(W);

    for (int it = 0; it < 3; it++) {
        s_gemm<<<dim3(2, 2, 36), 256, GEMM_SMEM>>>(x, it);
        if (it < 2) {
            g_gemm<<<dim3(72, 2), 256, GEMM_SMEM>>>(x, it);
            uv_fuse<<<dim3(18, NJ), 512>>>(it);
        }
    }
    squash_out<<<16, 256>>>(out);
}

// round 16
// speedup vs baseline: 1.2258x; 1.0002x over previous
#include <cuda_runtime.h>
#include <cstddef>
#include <cstdint>

// Problem constants
#define NB   256            // batch
#define NU   8              // in_units
#define NI   1152           // in_size
#define NJ   10             // out_units
#define ND   16             // out_size
#define NJD  (NJ*ND)        // 160
#define NK   (NU*NI)        // 9216
#define NM   (NJD*NU)       // 1280
#define NPART 18            // exp partial-sums per j (uv_fuse i-blocks)

// Packed fp32x2 helpers (Blackwell sm_103a)
#define FMA_F32X2(acc, a, b) \
    asm("fma.rn.f32x2 %0, %1, %2, %0;" : "+l"(acc) : "l"(a), "l"(b))
#define UNPACK2(lo, hi, in) \
    asm("mov.b64 {%0, %1}, %2;" : "=r"(lo), "=r"(hi) : "l"(in))

// GEMM smem (floats): wide tile [2][32][ASP], dup splat tile [2][32][BSP]
#define ASP    132              // 128 + pad
#define BSP    162              // 80*2 dup + pad
#define AS_F   (2 * 32 * ASP)   // 8448
#define BS_F   (2 * 32 * BSP)   // 10368
#define GEMM_SMEM ((AS_F + BS_F) * 4)   // 75264 B

// Scratch (device globals; allocation-free per harness rules)
__device__ float g_WT  [(size_t)NJD * NU * NI];  // [jd][u][i]  5.9 MB
__device__ float g_G   [(size_t)NJD * NU * NI];  // [jd][u][i]  5.9 MB
__device__ float g_s   [3 * NB * NJD];           // per-iteration s slices
__device__ float g_b   [NJ * NI];                // logits after it0 update [j][i]
__device__ float g_e   [3 * NJ * NI];            // unnormalized exp(b) per iter [j][i]
__device__ float g_part[3 * NJ * NPART];         // per-(iter,j) partial exp-sums

// ---------------------------------------------------------------------------
// Kernel 0 (once per replay): WT[m][i] = W[i][m]; zero g_s; init e/partials
// for iteration 0 (uniform softmax: e=1, NPART partials of 64 -> sum=1152).
// ---------------------------------------------------------------------------
__global__ void prep_kernel(const float* __restrict__ W) {
    __shared__ float t[32][33];
    const int i0 = blockIdx.x * 32, m0 = blockIdx.y * 32;
    const int tx = threadIdx.x, ty = threadIdx.y;
#pragma unroll
    for (int r = 0; r < 4; r++) {
        int i = i0 + ty + 8 * r;
        t[ty + 8 * r][tx] = W[(size_t)i * NM + m0 + tx];
    }
    __syncthreads();
#pragma unroll
    for (int r = 0; r < 4; r++) {
        int m = m0 + ty + 8 * r;
        g_WT[(size_t)m * NI + i0 + tx] = t[tx][ty + 8 * r];
    }

    const int flat = blockIdx.y * gridDim.x + blockIdx.x;   // 0..1439
    const int tid  = ty * 32 + tx;
    if (flat < 480) {                    // zero 3*40960 g_s floats
        g_s[flat * 256 + tid] = 0.0f;
    } else if (flat < 525) {             // e slot 0 = 1.0 (11520 floats)
        g_e[(flat - 480) * 256 + tid] = 1.0f;
    } else if (flat == 525) {            // partials slot 0 = 64 (sum 1152)
        if (tid < NJ * NPART) g_part[tid] = 64.0f;
    }
}

// ---------------------------------------------------------------------------
// Kernel 1: s_{it}[b,jd] += inv_j * sum_k x[b,k] * e[it][j,i(k)] * WT[jd,k]
// inv_j applied in the EPILOGUE. M=256 x N=160 x K=9216, split-K x36.
// grid (2,2,36), block 256. CTA 128b x 80jd; thread 8b x 5jd.
// NEW: inner loop software-pipelined one kk ahead (LDS latency hiding).
// ---------------------------------------------------------------------------
__global__ __launch_bounds__(256) void s_gemm(const float* __restrict__ x, int it) {
    extern __shared__ float sm[];
    float* As = sm;            // [2][32][ASP]  [k][b]
    float* Bs = sm + AS_F;     // [2][32][BSP]  [k][2*jd_local] duplicated
    __shared__ float inv_sm[5];

    const int t   = threadIdx.x;
    const int tx  = t & 15;              // 16 jd-groups of 5
    const int ty  = t >> 4;              // 16 b-groups of 8
    const int b0  = blockIdx.x * 128;
    const int jd0 = blockIdx.y * 80;
    const int k0  = blockIdx.z * 256;
    const int j_lo = jd0 >> 4;
    const int i_base = k0 % NI;          // chunk crosses NI boundary <= once

    if (t < 5) {
        const float* pp = g_part + it * (NJ * NPART) + (j_lo + t) * NPART;
        float s = 0.f;
#pragma unroll
        for (int r = 0; r < NPART; r++) s += pp[r];
        inv_sm[t] = 1.0f / s;
    }

    unsigned long long acc2[4][5];
#pragma unroll
    for (int p = 0; p < 4; p++)
#pragma unroll
        for (int q = 0; q < 5; q++) acc2[p][q] = 0ULL;

    float4 af[4];
    float  bf[10];
    const float* e_it = g_e + it * (NJ * NI);

    auto fetch = [&](int kb) {
        const int kbase = k0 + kb * 32;
        const int ibase = i_base + kb * 32;
#pragma unroll
        for (int r = 0; r < 4; r++) {
            int idx4 = t + 256 * r;                 // 1024 f4 = 128b x 8k4
            int bl = idx4 >> 3, k4 = idx4 & 7;
            af[r] = *(const float4*)&x[(size_t)(b0 + bl) * NK + kbase + k4 * 4];
        }
#pragma unroll
        for (int r = 0; r < 10; r++) {
            int idx = t + 256 * r;                  // 2560 = 32k x 80jd
            int kk = idx & 31, col = idx >> 5;
            int i  = ibase + kk;
            if (i >= NI) i -= NI;
            int jd = jd0 + col;
            int j  = jd >> 4;
            bf[r] = g_WT[(size_t)jd * NK + kbase + kk] * e_it[j * NI + i];
        }
    };
    auto sts = [&](int buf) {
        float* Ab = As + buf * 32 * ASP;
        float* Bb = Bs + buf * 32 * BSP;
#pragma unroll
        for (int r = 0; r < 4; r++) {
            int idx4 = t + 256 * r;
            int bl = idx4 >> 3, k4 = idx4 & 7;
            Ab[(k4 * 4 + 0) * ASP + bl] = af[r].x;
            Ab[(k4 * 4 + 1) * ASP + bl] = af[r].y;
            Ab[(k4 * 4 + 2) * ASP + bl] = af[r].z;
            Ab[(k4 * 4 + 3) * ASP + bl] = af[r].w;
        }
#pragma unroll
        for (int r = 0; r < 10; r++) {
            int idx = t + 256 * r;
            int kk = idx & 31, col = idx >> 5;
            *(float2*)&Bb[kk * BSP + col * 2] = make_float2(bf[r], bf[r]);
        }
    };

    fetch(0);
    sts(0);
    __syncthreads();

    for (int kb = 0; kb < 8; kb++) {
        const int buf = kb & 1;
        if (kb < 7) fetch(kb + 1);
        const float* Ab = As + buf * 32 * ASP + ty * 8;
        const float* Bb = Bs + buf * 32 * BSP + tx * 10;   // (tx*5)*2

        // software pipeline: preload kk=0
        ulonglong2 a01 = *(const ulonglong2*)(Ab);
        ulonglong2 a23 = *(const ulonglong2*)(Ab + 4);
        unsigned long long bb[5];
#pragma unroll
        for (int q = 0; q < 5; q++)
            bb[q] = *(const unsigned long long*)(Bb + 2 * q);

#pragma unroll
        for (int kk = 0; kk < 32; kk++) {
            ulonglong2 na01, na23;
            unsigned long long nbb[5];
            if (kk < 31) {
                const float* Abn = Ab + (kk + 1) * ASP;
                const float* Bbn = Bb + (kk + 1) * BSP;
                na01 = *(const ulonglong2*)(Abn);
                na23 = *(const ulonglong2*)(Abn + 4);
#pragma unroll
                for (int q = 0; q < 5; q++)
                    nbb[q] = *(const unsigned long long*)(Bbn + 2 * q);
            }
#pragma unroll
            for (int q = 0; q < 5; q++) {
                FMA_F32X2(acc2[0][q], a01.x, bb[q]);
                FMA_F32X2(acc2[1][q], a01.y, bb[q]);
                FMA_F32X2(acc2[2][q], a23.x, bb[q]);
                FMA_F32X2(acc2[3][q], a23.y, bb[q]);
            }
            if (kk < 31) {
                a01 = na01;
                a23 = na23;
#pragma unroll
                for (int q = 0; q < 5; q++) bb[q] = nbb[q];
            }
        }
        if (kb < 7) {
            sts(buf ^ 1);
            __syncthreads();
        }
    }

    float* sdst = g_s + it * (NB * NJD);
#pragma unroll
    for (int p = 0; p < 4; p++)
#pragma unroll
        for (int q = 0; q < 5; q++) {
            unsigned lo, hi;
            UNPACK2(lo, hi, acc2[p][q]);
            const int jd = jd0 + tx * 5 + q;
            const float inv = inv_sm[(jd >> 4) - j_lo];
            const int b  = b0 + ty * 8 + 2 * p;
            atomicAdd(&sdst[b * NJD + jd], __uint_as_float(lo) * inv);
            atomicAdd(&sdst[(b + 1) * NJD + jd], __uint_as_float(hi) * inv);
        }
}

// ---------------------------------------------------------------------------
// Kernel 2: G[m, n] = sum_b v[b,m] * x[b,n], v from in-prologue squash.
// M=160 x N=9216 x K=256. grid (72,2), block 256. CTA 80m x 128n; thr 5m x 8n.
// NEW: same one-kk-ahead software pipeline.
// ---------------------------------------------------------------------------
__global__ __launch_bounds__(256) void g_gemm(const float* __restrict__ x, int it) {
    extern __shared__ float sm[];
    float* Xs = sm;            // [2][32][ASP]
    float* Vs = sm + AS_F;     // [2][32][BSP] duplicated
    __shared__ float scale_sm[NB * ND];   // 16 KB

    const int t  = threadIdx.x;
    const int tx = t & 15;               // 16 m-groups of 5
    const int ty = t >> 4;               // 16 n-groups of 8
    const int n0 = blockIdx.x * 128;
    const int m0 = blockIdx.y * 80;
    const float* s_it = g_s + it * (NB * NJD);

    // squash scales for all (b,d)
    for (int bd = t; bd < NB * ND; bd += 256) {
        const int b = bd >> 4, d = bd & 15;
        const float* sp = s_it + b * NJD + d;
        float msq = 0.f;
#pragma unroll
        for (int j = 0; j < NJ; j++) {
            float v = sp[j * ND];
            msq = fmaf(v, v, msq);
        }
        scale_sm[bd] = sqrtf(msq) / (1.0f + msq);
    }
    __syncthreads();

    unsigned long long acc2[4][5];
#pragma unroll
    for (int p = 0; p < 4; p++)
#pragma unroll
        for (int q = 0; q < 5; q++) acc2[p][q] = 0ULL;

    float4 xf[4];
    float  vf[10];

    auto fetch = [&](int kb) {
        const int kbase = kb * 32;
#pragma unroll
        for (int r = 0; r < 4; r++) {
            int idx4 = t + 256 * r;                 // 1024 f4 = 32k x 32n4
            int kk = idx4 >> 5, n4 = idx4 & 31;
            xf[r] = *(const float4*)&x[(size_t)(kbase + kk) * NK + n0 + n4 * 4];
        }
#pragma unroll
        for (int r = 0; r < 10; r++) {
            int idx = t + 256 * r;                  // 2560 = 32k x 80m
            int col = idx % 80, kk = idx / 80;
            int b = kbase + kk, m = m0 + col;
            vf[r] = s_it[b * NJD + m] * scale_sm[(b << 4) | (m & 15)];
        }
    };
    auto sts = [&](int buf) {
        float* Xb = Xs + buf * 32 * ASP;
        float* Vb = Vs + buf * 32 * BSP;
#pragma unroll
        for (int r = 0; r < 4; r++) {
            int idx4 = t + 256 * r;
            int kk = idx4 >> 5, n4 = idx4 & 31;
            *(float4*)&Xb[kk * ASP + n4 * 4] = xf[r];
        }
#pragma unroll
        for (int r = 0; r < 10; r++) {
            int idx = t + 256 * r;
            int col = idx % 80, kk = idx / 80;
            *(float2*)&Vb[kk * BSP + col * 2] = make_float2(vf[r], vf[r]);
        }
    };

    fetch(0);
    sts(0);
    __syncthreads();

    for (int kb = 0; kb < 8; kb++) {
        const int buf = kb & 1;
        if (kb < 7) fetch(kb + 1);
        const float* Xb = Xs + buf * 32 * ASP + ty * 8;
        const float* Vb = Vs + buf * 32 * BSP + tx * 10;

        ulonglong2 x01 = *(const ulonglong2*)(Xb);
        ulonglong2 x23 = *(const ulonglong2*)(Xb + 4);
        unsigned long long vv[5];
#pragma unroll
        for (int q = 0; q < 5; q++)
            vv[q] = *(const unsigned long long*)(Vb + 2 * q);

#pragma unroll
        for (int kk = 0; kk < 32; kk++) {
            ulonglong2 nx01, nx23;
            unsigned long long nvv[5];
            if (kk < 31) {
                const float* Xbn = Xb + (kk + 1) * ASP;
                const float* Vbn = Vb + (kk + 1) * BSP;
                nx01 = *(const ulonglong2*)(Xbn);
                nx23 = *(const ulonglong2*)(Xbn + 4);
#pragma unroll
                for (int q = 0; q < 5; q++)
                    nvv[q] = *(const unsigned long long*)(Vbn + 2 * q);
            }
#pragma unroll
            for (int q = 0; q < 5; q++) {
                FMA_F32X2(acc2[0][q], x01.x, vv[q]);
                FMA_F32X2(acc2[1][q], x01.y, vv[q]);
                FMA_F32X2(acc2[2][q], x23.x, vv[q]);
                FMA_F32X2(acc2[3][q], x23.y, vv[q]);
            }
            if (kk < 31) {
                x01 = nx01;
                x23 = nx23;
#pragma unroll
                for (int q = 0; q < 5; q++) vv[q] = nvv[q];
            }
        }
        if (kb < 7) {
            sts(buf ^ 1);
            __syncthreads();
        }
    }

#pragma unroll
    for (int q = 0; q < 5; q++) {
        const int m = m0 + tx * 5 + q;
        unsigned l0, h0, l1, h1, l2, h2, l3, h3;
        UNPACK2(l0, h0, acc2[0][q]);
        UNPACK2(l1, h1, acc2[1][q]);
        UNPACK2(l2, h2, acc2[2][q]);
        UNPACK2(l3, h3, acc2[3][q]);
        float4 o0, o1;
        o0.x = __uint_as_float(l0); o0.y = __uint_as_float(h0);
        o0.z = __uint_as_float(l1); o0.w = __uint_as_float(h1);
        o1.x = __uint_as_float(l2); o1.y = __uint_as_float(h2);
        o1.z = __uint_as_float(l3); o1.w = __uint_as_float(h3);
        float* dst = &g_G[(size_t)m * NK + n0 + ty * 8];
        *(float4*)dst = o0;
        *(float4*)(dst + 4) = o1;
    }
}

// ---------------------------------------------------------------------------
// Kernel 3: fused agreement + b-update + exp + partial sums. (r11-proven)
// grid (18, 10), block 512: 64 i's per CTA, 8 m-groups of 16 per thread.
// ---------------------------------------------------------------------------
__global__ __launch_bounds__(512) void uv_fuse(int it) {
    const int t   = threadIdx.x;
    const int il  = t & 63;            // i within block
    const int grp = t >> 6;            // 8 m-groups of 16
    const int i = blockIdx.x * 64 + il;
    const int j = blockIdx.y;

    const size_t base = (size_t)(j * 128 + grp * 16) * NI + i;
    float acc = 0.f;
#pragma unroll
    for (int m = 0; m < 16; m++) {
        acc = fmaf(g_WT[base + (size_t)m * NI], g_G[base + (size_t)m * NI], acc);
    }

    __shared__ float red[8][64];
    __shared__ float esum[64];
    red[grp][il] = acc;
    __syncthreads();
    if (grp < 4) red[grp][il] += red[grp + 4][il];
    __syncthreads();
    if (grp < 2) red[grp][il] += red[grp + 2][il];
    __syncthreads();
    if (grp == 0) {
        float uv = red[0][il] + red[1][il];
        float bv = (it == 0 ? 1.0f : g_b[j * NI + i]) + uv * (1.0f / (float)NB);
        if (it == 0) g_b[j * NI + i] = bv;
        float e = expf(bv);
        g_e[(it + 1) * (NJ * NI) + j * NI + i] = e;
        esum[il] = e;
    }
    __syncthreads();
    if (t < 32) {
        float v = esum[t] + esum[t + 32];
#pragma unroll
        for (int o = 16; o > 0; o >>= 1) v += __shfl_down_sync(0xffffffffu, v, o);
        if (t == 0)
            g_part[(it + 1) * (NJ * NPART) + j * NPART + blockIdx.x] = v;
    }
}

// ---------------------------------------------------------------------------
// Kernel 4: final squash -> d_out.  v = s * sqrt(msq)/(1+msq), msq over j.
// ---------------------------------------------------------------------------
__global__ void squash_out(float* __restrict__ out) {
    const int t = blockIdx.x * blockDim.x + threadIdx.x;
    if (t >= NB * ND) return;
    const int b = t >> 4, d = t & 15;

    const float* sp = g_s + 2 * (NB * NJD) + b * NJD + d;
    float vals[NJ];
    float msq = 0.f;
#pragma unroll
    for (int j = 0; j < NJ; j++) {
        vals[j] = sp[j * ND];
        msq = fmaf(vals[j], vals[j], msq);
    }
    const float scale = sqrtf(msq) / (1.0f + msq);
#pragma unroll
    for (int j = 0; j < NJ; j++) out[b * NJD + j * ND + d] = vals[j] * scale;
}

// ---------------------------------------------------------------------------
extern "C" void kernel_launch(void* const* d_in, const int* in_sizes, int n_in,
                              void* d_out, int out_size) {
    const float* x = (const float*)d_in[0];   // (256, 8, 1152)
    const float* W = (const float*)d_in[1];   // (1, 1152, 10, 16, 8)
    float* out = (float*)d_out;               // (256, 10, 16, 1)

    static bool attr_set = false;
    if (!attr_set) {
        cudaFuncSetAttribute(s_gemm, cudaFuncAttributeMaxDynamicSharedMemorySize,
                             GEMM_SMEM);
        cudaFuncSetAttribute(g_gemm, cudaFuncAttributeMaxDynamicSharedMemorySize,
                             GEMM_SMEM);
        attr_set = true;
    }

    prep_kernel<<<dim3(36, 40), dim3(32, 8)>>>(W);

    for (int it = 0; it < 3; it++) {
        s_gemm<<<dim3(2, 2, 36), 256, GEMM_SMEM>>>(x, it);
        if (it < 2) {
            g_gemm<<<dim3(72, 2), 256, GEMM_SMEM>>>(x, it);
            uv_fuse<<<dim3(18, NJ), 512>>>(it);
        }
    }
    squash_out<<<16, 256>>>(out);
}

// round 17
// speedup vs baseline: 1.2292x; 1.0028x over previous
#include <cuda_runtime.h>
#include <cstddef>
#include <cstdint>

// Problem constants
#define NB   256            // batch
#define NU   8              // in_units
#define NI   1152           // in_size
#define NJ   10             // out_units
#define ND   16             // out_size
#define NJD  (NJ*ND)        // 160
#define NK   (NU*NI)        // 9216
#define NM   (NJD*NU)       // 1280
#define NPART 18            // exp partial-sums per j (uv_fuse i-blocks)

// Packed fp32x2 helpers (Blackwell sm_103a)
#define FMA_F32X2(acc, a, b) \
    asm("fma.rn.f32x2 %0, %1, %2, %0;" : "+l"(acc) : "l"(a), "l"(b))
#define UNPACK2(lo, hi, in) \
    asm("mov.b64 {%0, %1}, %2;" : "=r"(lo), "=r"(hi) : "l"(in))

// GEMM smem (floats): wide tile [2][32][ASP], dup splat tile [2][32][BSP]
#define ASP    132              // 128 + pad
#define BSP    164              // 80*2 dup + pad (multiple of 4 for STS.128)
#define AS_F   (2 * 32 * ASP)   // 8448
#define BS_F   (2 * 32 * BSP)   // 10496
#define GEMM_SMEM ((AS_F + BS_F) * 4)   // 75776 B

// Scratch (device globals; allocation-free per harness rules)
__device__ float g_WT  [(size_t)NJD * NU * NI];  // [jd][u][i]  5.9 MB
__device__ float g_G   [(size_t)NJD * NU * NI];  // [jd][u][i]  5.9 MB
__device__ float g_s   [3 * NB * NJD];           // per-iteration s slices
__device__ float g_b   [NJ * NI];                // logits after it0 update [j][i]
__device__ float g_e   [3 * NJ * NI];            // unnormalized exp(b) per iter [j][i]
__device__ float g_part[3 * NJ * NPART];         // per-(iter,j) partial exp-sums

// ---------------------------------------------------------------------------
// Kernel 0 (once per replay): WT[m][i] = W[i][m]; zero g_s; init e/partials
// for iteration 0 (uniform softmax: e=1, NPART partials of 64 -> sum=1152).
// ---------------------------------------------------------------------------
__global__ void prep_kernel(const float* __restrict__ W) {
    __shared__ float t[32][33];
    const int i0 = blockIdx.x * 32, m0 = blockIdx.y * 32;
    const int tx = threadIdx.x, ty = threadIdx.y;
#pragma unroll
    for (int r = 0; r < 4; r++) {
        int i = i0 + ty + 8 * r;
        t[ty + 8 * r][tx] = W[(size_t)i * NM + m0 + tx];
    }
    __syncthreads();
#pragma unroll
    for (int r = 0; r < 4; r++) {
        int m = m0 + ty + 8 * r;
        g_WT[(size_t)m * NI + i0 + tx] = t[tx][ty + 8 * r];
    }

    const int flat = blockIdx.y * gridDim.x + blockIdx.x;   // 0..1439
    const int tid  = ty * 32 + tx;
    if (flat < 480) {                    // zero 3*40960 g_s floats
        g_s[flat * 256 + tid] = 0.0f;
    } else if (flat < 525) {             // e slot 0 = 1.0 (11520 floats)
        g_e[(flat - 480) * 256 + tid] = 1.0f;
    } else if (flat == 525) {            // partials slot 0 = 64 (sum 1152)
        if (tid < NJ * NPART) g_part[tid] = 64.0f;
    }
}

// ---------------------------------------------------------------------------
// Kernel 1: s_{it}[b,jd] += inv_j * sum_k x[b,k] * e[it][j,i(k)] * WT[jd,k]
// inv_j applied in the EPILOGUE. M=256 x N=160 x K=9216, split-K x36.
// grid (2,2,36), block 256. CTA 128b x 80jd; thread 8b x 5jd.
// NEW: B-side fetch vectorized over kk-pairs (LDG.64), halving LDG count.
// ---------------------------------------------------------------------------
__global__ __launch_bounds__(256) void s_gemm(const float* __restrict__ x, int it) {
    extern __shared__ float sm[];
    float* As = sm;            // [2][32][ASP]  [k][b]
    float* Bs = sm + AS_F;     // [2][32][BSP]  [k][2*jd_local] duplicated
    __shared__ float inv_sm[5];

    const int t   = threadIdx.x;
    const int tx  = t & 15;              // 16 jd-groups of 5
    const int ty  = t >> 4;              // 16 b-groups of 8
    const int b0  = blockIdx.x * 128;
    const int jd0 = blockIdx.y * 80;
    const int k0  = blockIdx.z * 256;
    const int j_lo = jd0 >> 4;
    const int i_base = k0 % NI;          // chunk crosses NI boundary <= once

    if (t < 5) {
        const float* pp = g_part + it * (NJ * NPART) + (j_lo + t) * NPART;
        float s = 0.f;
#pragma unroll
        for (int r = 0; r < NPART; r++) s += pp[r];
        inv_sm[t] = 1.0f / s;
    }

    unsigned long long acc2[4][5];
#pragma unroll
    for (int p = 0; p < 4; p++)
#pragma unroll
        for (int q = 0; q < 5; q++) acc2[p][q] = 0ULL;

    float4 af[4];
    float2 bf2[5];
    const float* e_it = g_e + it * (NJ * NI);

    auto fetch = [&](int kb) {
        const int kbase = k0 + kb * 32;
        const int ibase = i_base + kb * 32;
#pragma unroll
        for (int r = 0; r < 4; r++) {
            int idx4 = t + 256 * r;                 // 1024 f4 = 128b x 8k4
            int bl = idx4 >> 3, k4 = idx4 & 7;
            af[r] = *(const float4*)&x[(size_t)(b0 + bl) * NK + kbase + k4 * 4];
        }
#pragma unroll
        for (int r = 0; r < 5; r++) {
            int idx2 = t + 256 * r;                 // 1280 f2 = 16kk2 x 80jd
            int kk2 = idx2 & 15, col = idx2 >> 4;
            int kk  = kk2 * 2;
            int i   = ibase + kk;                   // even; pairs never straddle
            if (i >= NI) i -= NI;
            int jd = jd0 + col;
            int j  = jd >> 4;
            float2 wt2 = *(const float2*)&g_WT[(size_t)jd * NK + kbase + kk];
            float2 e2  = *(const float2*)&e_it[j * NI + i];
            bf2[r].x = wt2.x * e2.x;
            bf2[r].y = wt2.y * e2.y;
        }
    };
    auto sts = [&](int buf) {
        float* Ab = As + buf * 32 * ASP;
        float* Bb = Bs + buf * 32 * BSP;
#pragma unroll
        for (int r = 0; r < 4; r++) {
            int idx4 = t + 256 * r;
            int bl = idx4 >> 3, k4 = idx4 & 7;
            Ab[(k4 * 4 + 0) * ASP + bl] = af[r].x;
            Ab[(k4 * 4 + 1) * ASP + bl] = af[r].y;
            Ab[(k4 * 4 + 2) * ASP + bl] = af[r].z;
            Ab[(k4 * 4 + 3) * ASP + bl] = af[r].w;
        }
#pragma unroll
        for (int r = 0; r < 5; r++) {
            int idx2 = t + 256 * r;
            int kk2 = idx2 & 15, col = idx2 >> 4;
            int kk  = kk2 * 2;
            *(float2*)&Bb[kk * BSP + col * 2]       = make_float2(bf2[r].x, bf2[r].x);
            *(float2*)&Bb[(kk + 1) * BSP + col * 2] = make_float2(bf2[r].y, bf2[r].y);
        }
    };

    fetch(0);
    sts(0);
    __syncthreads();

    for (int kb = 0; kb < 8; kb++) {
        const int buf = kb & 1;
        if (kb < 7) fetch(kb + 1);
        const float* Ab = As + buf * 32 * ASP;
        const float* Bb = Bs + buf * 32 * BSP;
#pragma unroll
        for (int kk = 0; kk < 32; kk++) {
            const float* arow = Ab + kk * ASP + ty * 8;
            ulonglong2 a01 = *(const ulonglong2*)arow;
            ulonglong2 a23 = *(const ulonglong2*)(arow + 4);
#pragma unroll
            for (int q = 0; q < 5; q++) {
                unsigned long long bb =
                    *(const unsigned long long*)&Bb[kk * BSP + (tx * 5 + q) * 2];
                FMA_F32X2(acc2[0][q], a01.x, bb);
                FMA_F32X2(acc2[1][q], a01.y, bb);
                FMA_F32X2(acc2[2][q], a23.x, bb);
                FMA_F32X2(acc2[3][q], a23.y, bb);
            }
        }
        if (kb < 7) {
            sts(buf ^ 1);
            __syncthreads();
        }
    }

    float* sdst = g_s + it * (NB * NJD);
#pragma unroll
    for (int p = 0; p < 4; p++)
#pragma unroll
        for (int q = 0; q < 5; q++) {
            unsigned lo, hi;
            UNPACK2(lo, hi, acc2[p][q]);
            const int jd = jd0 + tx * 5 + q;
            const float inv = inv_sm[(jd >> 4) - j_lo];
            const int b  = b0 + ty * 8 + 2 * p;
            atomicAdd(&sdst[b * NJD + jd], __uint_as_float(lo) * inv);
            atomicAdd(&sdst[(b + 1) * NJD + jd], __uint_as_float(hi) * inv);
        }
}

// ---------------------------------------------------------------------------
// Kernel 2: G[m, n] = sum_b v[b,m] * x[b,n], v from in-prologue squash.
// M=160 x N=9216 x K=256. grid (72,2), block 256. CTA 80m x 128n; thr 5m x 8n.
// NEW: V fetch vectorized over m-pairs (LDG.64) with STS.128 dup-stores;
//      squash prologue vectorized over d-pairs.
// ---------------------------------------------------------------------------
__global__ __launch_bounds__(256) void g_gemm(const float* __restrict__ x, int it) {
    extern __shared__ float sm[];
    float* Xs = sm;            // [2][32][ASP]
    float* Vs = sm + AS_F;     // [2][32][BSP] duplicated
    __shared__ float scale_sm[NB * ND];   // 16 KB

    const int t  = threadIdx.x;
    const int tx = t & 15;               // 16 m-groups of 5
    const int ty = t >> 4;               // 16 n-groups of 8
    const int n0 = blockIdx.x * 128;
    const int m0 = blockIdx.y * 80;
    const float* s_it = g_s + it * (NB * NJD);

    // squash scales for all (b,d), two d's per thread-step
    for (int bd2 = t; bd2 < (NB * ND) / 2; bd2 += 256) {
        const int b = bd2 >> 3;
        const int d = (bd2 & 7) << 1;
        const float* sp = s_it + b * NJD + d;
        float m0q = 0.f, m1q = 0.f;
#pragma unroll
        for (int j = 0; j < NJ; j++) {
            float2 v = *(const float2*)&sp[j * ND];
            m0q = fmaf(v.x, v.x, m0q);
            m1q = fmaf(v.y, v.y, m1q);
        }
        float2 sc;
        sc.x = sqrtf(m0q) / (1.0f + m0q);
        sc.y = sqrtf(m1q) / (1.0f + m1q);
        *(float2*)&scale_sm[(b << 4) | d] = sc;
    }
    __syncthreads();

    unsigned long long acc2[4][5];
#pragma unroll
    for (int p = 0; p < 4; p++)
#pragma unroll
        for (int q = 0; q < 5; q++) acc2[p][q] = 0ULL;

    float4 xf[4];
    float2 vf2[5];

    auto fetch = [&](int kb) {
        const int kbase = kb * 32;
#pragma unroll
        for (int r = 0; r < 4; r++) {
            int idx4 = t + 256 * r;                 // 1024 f4 = 32k x 32n4
            int kk = idx4 >> 5, n4 = idx4 & 31;
            xf[r] = *(const float4*)&x[(size_t)(kbase + kk) * NK + n0 + n4 * 4];
        }
#pragma unroll
        for (int r = 0; r < 5; r++) {
            int idx2 = t + 256 * r;                 // 1280 f2 = 32kk x 40 colp
            int colp = idx2 % 40, kk = idx2 / 40;
            int b = kbase + kk, m = m0 + colp * 2;
            float2 sv = *(const float2*)&s_it[b * NJD + m];
            vf2[r].x = sv.x * scale_sm[(b << 4) | (m & 15)];
            vf2[r].y = sv.y * scale_sm[(b << 4) | ((m + 1) & 15)];
        }
    };
    auto sts = [&](int buf) {
        float* Xb = Xs + buf * 32 * ASP;
        float* Vb = Vs + buf * 32 * BSP;
#pragma unroll
        for (int r = 0; r < 4; r++) {
            int idx4 = t + 256 * r;
            int kk = idx4 >> 5, n4 = idx4 & 31;
            *(float4*)&Xb[kk * ASP + n4 * 4] = xf[r];
        }
#pragma unroll
        for (int r = 0; r < 5; r++) {
            int idx2 = t + 256 * r;
            int colp = idx2 % 40, kk = idx2 / 40;
            *(float4*)&Vb[kk * BSP + colp * 4] =
                make_float4(vf2[r].x, vf2[r].x, vf2[r].y, vf2[r].y);
        }
    };

    fetch(0);
    sts(0);
    __syncthreads();

    for (int kb = 0; kb < 8; kb++) {
        const int buf = kb & 1;
        if (kb < 7) fetch(kb + 1);
        const float* Xb = Xs + buf * 32 * ASP;
        const float* Vb = Vs + buf * 32 * BSP;
#pragma unroll
        for (int kk = 0; kk < 32; kk++) {
            const float* xrow = Xb + kk * ASP + ty * 8;
            ulonglong2 x01 = *(const ulonglong2*)xrow;
            ulonglong2 x23 = *(const ulonglong2*)(xrow + 4);
#pragma unroll
            for (int q = 0; q < 5; q++) {
                unsigned long long vv =
                    *(const unsigned long long*)&Vb[kk * BSP + (tx * 5 + q) * 2];
                FMA_F32X2(acc2[0][q], x01.x, vv);
                FMA_F32X2(acc2[1][q], x01.y, vv);
                FMA_F32X2(acc2[2][q], x23.x, vv);
                FMA_F32X2(acc2[3][q], x23.y, vv);
            }
        }
        if (kb < 7) {
            sts(buf ^ 1);
            __syncthreads();
        }
    }

#pragma unroll
    for (int q = 0; q < 5; q++) {
        const int m = m0 + tx * 5 + q;
        unsigned l0, h0, l1, h1, l2, h2, l3, h3;
        UNPACK2(l0, h0, acc2[0][q]);
        UNPACK2(l1, h1, acc2[1][q]);
        UNPACK2(l2, h2, acc2[2][q]);
        UNPACK2(l3, h3, acc2[3][q]);
        float4 o0, o1;
        o0.x = __uint_as_float(l0); o0.y = __uint_as_float(h0);
        o0.z = __uint_as_float(l1); o0.w = __uint_as_float(h1);
        o1.x = __uint_as_float(l2); o1.y = __uint_as_float(h2);
        o1.z = __uint_as_float(l3); o1.w = __uint_as_float(h3);
        float* dst = &g_G[(size_t)m * NK + n0 + ty * 8];
        *(float4*)dst = o0;
        *(float4*)(dst + 4) = o1;
    }
}

// ---------------------------------------------------------------------------
// Kernel 3: fused agreement + b-update + exp + partial sums. (r11-proven)
// grid (18, 10), block 512: 64 i's per CTA, 8 m-groups of 16 per thread.
// ---------------------------------------------------------------------------
__global__ __launch_bounds__(512) void uv_fuse(int it) {
    const int t   = threadIdx.x;
    const int il  = t & 63;            // i within block
    const int grp = t >> 6;            // 8 m-groups of 16
    const int i = blockIdx.x * 64 + il;
    const int j = blockIdx.y;

    const size_t base = (size_t)(j * 128 + grp * 16) * NI + i;
    float acc = 0.f;
#pragma unroll
    for (int m = 0; m < 16; m++) {
        acc = fmaf(g_WT[base + (size_t)m * NI], g_G[base + (size_t)m * NI], acc);
    }

    __shared__ float red[8][64];
    __shared__ float esum[64];
    red[grp][il] = acc;
    __syncthreads();
    if (grp < 4) red[grp][il] += red[grp + 4][il];
    __syncthreads();
    if (grp < 2) red[grp][il] += red[grp + 2][il];
    __syncthreads();
    if (grp == 0) {
        float uv = red[0][il] + red[1][il];
        float bv = (it == 0 ? 1.0f : g_b[j * NI + i]) + uv * (1.0f / (float)NB);
        if (it == 0) g_b[j * NI + i] = bv;
        float e = expf(bv);
        g_e[(it + 1) * (NJ * NI) + j * NI + i] = e;
        esum[il] = e;
    }
    __syncthreads();
    if (t < 32) {
        float v = esum[t] + esum[t + 32];
#pragma unroll
        for (int o = 16; o > 0; o >>= 1) v += __shfl_down_sync(0xffffffffu, v, o);
        if (t == 0)
            g_part[(it + 1) * (NJ * NPART) + j * NPART + blockIdx.x] = v;
    }
}

// ---------------------------------------------------------------------------
// Kernel 4: final squash -> d_out.  v = s * sqrt(msq)/(1+msq), msq over j.
// ---------------------------------------------------------------------------
__global__ void squash_out(float* __restrict__ out) {
    const int t = blockIdx.x * blockDim.x + threadIdx.x;
    if (t >= NB * ND) return;
    const int b = t >> 4, d = t & 15;

    const float* sp = g_s + 2 * (NB * NJD) + b * NJD + d;
    float vals[NJ];
    float msq = 0.f;
#pragma unroll
    for (int j = 0; j < NJ; j++) {
        vals[j] = sp[j * ND];
        msq = fmaf(vals[j], vals[j], msq);
    }
    const float scale = sqrtf(msq) / (1.0f + msq);
#pragma unroll
    for (int j = 0; j < NJ; j++) out[b * NJD + j * ND + d] = vals[j] * scale;
}

// ---------------------------------------------------------------------------
extern "C" void kernel_launch(void* const* d_in, const int* in_sizes, int n_in,
                              void* d_out, int out_size) {
    const float* x = (const float*)d_in[0];   // (256, 8, 1152)
    const float* W = (const float*)d_in[1];   // (1, 1152, 10, 16, 8)
    float* out = (float*)d_out;               // (256, 10, 16, 1)

    static bool attr_set = false;
    if (!attr_set) {
        cudaFuncSetAttribute(s_gemm, cudaFuncAttributeMaxDynamicSharedMemorySize,
                             GEMM_SMEM);
        cudaFuncSetAttribute(g_gemm, cudaFuncAttributeMaxDynamicSharedMemorySize,
                             GEMM_SMEM);
        attr_set = true;
    }

    prep_kernel<<<dim3(36, 40), dim3(32, 8)>>>(W);

    for (int it = 0; it < 3; it++) {
        s_gemm<<<dim3(2, 2, 36), 256, GEMM_SMEM>>>(x, it);
        if (it < 2) {
            g_gemm<<<dim3(72, 2), 256, GEMM_SMEM>>>(x, it);
            uv_fuse<<<dim3(18, NJ), 512>>>(it);
        }
    }
    squash_out<<<16, 256>>>(out);
}